// round 2
// baseline (speedup 1.0000x reference)
#include <cuda_runtime.h>
#include <math.h>

static constexpr int B_ = 2, S_ = 2048, E_ = 2048, H_ = 16, D_ = 128;
static constexpr int M_ = B_ * S_;   // 4096
static constexpr int N_ = E_;        // 2048
static constexpr int K_ = E_;        // 2048

// Scratch (allocation-free rule: __device__ globals)
__device__ float g_Qp[B_*H_*S_*D_];
__device__ float g_Kp[B_*H_*S_*D_];
__device__ float g_Vp[B_*H_*S_*D_];
__device__ float g_ctx[B_*S_*E_];

// ---------------------------------------------------------------------------
// C = A(M x K) @ W(N x K)^T.  split=1: write head-split layout (B,H,S,D) with scale.
// 128x128x16 tile, 256 threads, 8x8 micro-tile in 4 quadrants (conflict-free LDS.128)
// ---------------------------------------------------------------------------
__global__ __launch_bounds__(256, 2)
void gemm_xwT(const float* __restrict__ A, const float* __restrict__ W,
              float* __restrict__ C, int split, float scale)
{
    __shared__ float As[16][132];
    __shared__ float Bs[16][132];
    const int tid = threadIdx.x;
    const int tx = tid & 15;
    const int ty = tid >> 4;
    const int m0 = blockIdx.y * 128;
    const int n0 = blockIdx.x * 128;

    const int lrow = tid >> 2;        // 0..63
    const int lk = (tid & 3) * 4;     // 0,4,8,12

    const float* Ap = A + (size_t)(m0 + lrow) * K_ + lk;
    const float* Wp = W + (size_t)(n0 + lrow) * K_ + lk;

    float acc[8][8];
#pragma unroll
    for (int i = 0; i < 8; i++)
#pragma unroll
        for (int j = 0; j < 8; j++) acc[i][j] = 0.f;

    for (int k0 = 0; k0 < K_; k0 += 16) {
        float4 a0 = *(const float4*)(Ap + k0);
        float4 a1 = *(const float4*)(Ap + (size_t)64 * K_ + k0);
        float4 b0 = *(const float4*)(Wp + k0);
        float4 b1 = *(const float4*)(Wp + (size_t)64 * K_ + k0);
        __syncthreads();
        As[lk+0][lrow] = a0.x; As[lk+1][lrow] = a0.y; As[lk+2][lrow] = a0.z; As[lk+3][lrow] = a0.w;
        As[lk+0][lrow+64] = a1.x; As[lk+1][lrow+64] = a1.y; As[lk+2][lrow+64] = a1.z; As[lk+3][lrow+64] = a1.w;
        Bs[lk+0][lrow] = b0.x; Bs[lk+1][lrow] = b0.y; Bs[lk+2][lrow] = b0.z; Bs[lk+3][lrow] = b0.w;
        Bs[lk+0][lrow+64] = b1.x; Bs[lk+1][lrow+64] = b1.y; Bs[lk+2][lrow+64] = b1.z; Bs[lk+3][lrow+64] = b1.w;
        __syncthreads();
#pragma unroll
        for (int kk = 0; kk < 16; kk++) {
            float af[8], bf[8];
            *(float4*)(af)     = *(const float4*)&As[kk][ty*4];
            *(float4*)(af + 4) = *(const float4*)&As[kk][64 + ty*4];
            *(float4*)(bf)     = *(const float4*)&Bs[kk][tx*4];
            *(float4*)(bf + 4) = *(const float4*)&Bs[kk][64 + tx*4];
#pragma unroll
            for (int i = 0; i < 8; i++)
#pragma unroll
                for (int j = 0; j < 8; j++)
                    acc[i][j] = fmaf(af[i], bf[j], acc[i][j]);
        }
    }

    const int h = blockIdx.x;   // N-tile width == head dim count (128), so tile == one head
#pragma unroll
    for (int i = 0; i < 8; i++) {
        int r = m0 + ((i < 4) ? (ty*4 + i) : (64 + ty*4 + i - 4));
#pragma unroll
        for (int jh = 0; jh < 2; jh++) {
            int c = jh*64 + tx*4;
            float4 v;
            v.x = acc[i][jh*4+0]*scale; v.y = acc[i][jh*4+1]*scale;
            v.z = acc[i][jh*4+2]*scale; v.w = acc[i][jh*4+3]*scale;
            if (split) {
                int b = r >> 11, s = r & (S_ - 1);
                size_t o = (((size_t)(b*H_ + h))*S_ + s)*(size_t)D_ + c;
                *(float4*)(C + o) = v;
            } else {
                *(float4*)(C + (size_t)r*N_ + n0 + c) = v;
            }
        }
    }
}

// ---------------------------------------------------------------------------
// Flash attention, causal. Per block: 64 q-rows x full D=128, Bc=32 K/V tiles.
// 256 threads. Scores in registers (one exp per score), p staged via smem.
// ---------------------------------------------------------------------------
static constexpr int ATTN_SMEM = (64*128 + 32*128 + 32*128 + 64*33 + 3*64) * 4; // 74752 B

__device__ __forceinline__ float dot4(float4 a, float4 b, float acc) {
    acc = fmaf(a.x, b.x, acc);
    acc = fmaf(a.y, b.y, acc);
    acc = fmaf(a.z, b.z, acc);
    acc = fmaf(a.w, b.w, acc);
    return acc;
}

__global__ __launch_bounds__(256)
void attn_kernel(const float* __restrict__ Qp, const float* __restrict__ Kp,
                 const float* __restrict__ Vp, float* __restrict__ ctx)
{
    extern __shared__ float sm[];
    float4* Qs4 = (float4*)sm;               // 64 rows x 32 float4 (swizzled)
    float4* Ks4 = Qs4 + 64*32;               // 32 x 32 (swizzled)
    float4* Vs4 = Ks4 + 32*32;               // 32 x 32 (plain)
    float*  Sc  = (float*)(Vs4 + 32*32);     // 64 x 33
    float*  m_s = Sc + 64*33;
    float*  l_s = m_s + 64;
    float*  a_s = l_s + 64;

    const int tid = threadIdx.x;
    const int qt  = blockIdx.x;
    const int bh  = blockIdx.y;
    const int qr0 = qt * 64;

    if (tid < 64) { m_s[tid] = -1e30f; l_s[tid] = 0.f; }

    const float4* Qg = (const float4*)(Qp + ((size_t)bh * S_ + qr0) * D_);
#pragma unroll
    for (int r = 0; r < 8; r++) {
        int idx = tid + 256*r;
        int row = idx >> 5, c4 = idx & 31;
        Qs4[row*32 + ((c4 + (row >> 1)) & 31)] = Qg[idx];
    }

    // score-phase mapping: thread -> rows {sr, sr+1}, cols {sc..sc+3}
    const int sr = (tid >> 3) * 2;
    const int sc = (tid & 7) * 4;
    const int qoff = sr >> 1;
    const int koff = sc >> 2;
    const int qrow0 = qr0 + sr;
    const int qrow1 = qrow0 + 1;

    // O-phase mapping: thread -> rows {r0, r0+32}, cols [oc*16, oc*16+16)
    const int r0 = tid & 31, r1 = r0 + 32;
    const int oc = tid >> 5;                 // 0..7 (uniform per warp -> V broadcast)
    float4 o[2][4];
#pragma unroll
    for (int a = 0; a < 2; a++)
#pragma unroll
        for (int u = 0; u < 4; u++) o[a][u] = make_float4(0.f, 0.f, 0.f, 0.f);

    __syncthreads();

    const int nkt = 2*qt + 2;
    for (int kt = 0; kt < nkt; kt++) {
        const int k0 = kt * 32;
        const float4* Kg = (const float4*)(Kp + ((size_t)bh * S_ + k0) * D_);
        const float4* Vg = (const float4*)(Vp + ((size_t)bh * S_ + k0) * D_);
#pragma unroll
        for (int r = 0; r < 4; r++) {
            int idx = tid + 256*r;
            int row = idx >> 5, c4 = idx & 31;
            Ks4[row*32 + ((c4 + (row >> 2)) & 31)] = Kg[idx];
            Vs4[idx] = Vg[idx];
        }
        __syncthreads();

        // ---- scores: S = Q @ K^T (2x4 micro-tile per thread) ----
        float s0[4] = {0,0,0,0}, s1[4] = {0,0,0,0};
#pragma unroll
        for (int c4 = 0; c4 < 32; c4++) {
            int qp = (c4 + qoff) & 31;
            int kp = (c4 + koff) & 31;
            float4 qa  = Qs4[sr*32 + qp];
            float4 qb  = Qs4[(sr+1)*32 + qp];
            float4 k0v = Ks4[(sc+0)*32 + kp];
            float4 k1v = Ks4[(sc+1)*32 + kp];
            float4 k2v = Ks4[(sc+2)*32 + kp];
            float4 k3v = Ks4[(sc+3)*32 + kp];
            s0[0] = dot4(qa, k0v, s0[0]);
            s0[1] = dot4(qa, k1v, s0[1]);
            s0[2] = dot4(qa, k2v, s0[2]);
            s0[3] = dot4(qa, k3v, s0[3]);
            s1[0] = dot4(qb, k0v, s1[0]);
            s1[1] = dot4(qb, k1v, s1[1]);
            s1[2] = dot4(qb, k2v, s1[2]);
            s1[3] = dot4(qb, k3v, s1[3]);
        }

        // causal mask (reference's -1e4 mask underflows to exact 0 after softmax)
#pragma unroll
        for (int j = 0; j < 4; j++) {
            int kc = k0 + sc + j;
            if (kc > qrow0) s0[j] = -1e30f;
            if (kc > qrow1) s1[j] = -1e30f;
        }

        // online softmax: reduce max over the 8 lanes covering a row
        float mt0 = fmaxf(fmaxf(s0[0], s0[1]), fmaxf(s0[2], s0[3]));
        float mt1 = fmaxf(fmaxf(s1[0], s1[1]), fmaxf(s1[2], s1[3]));
#pragma unroll
        for (int off = 1; off < 8; off <<= 1) {
            mt0 = fmaxf(mt0, __shfl_xor_sync(0xffffffffu, mt0, off));
            mt1 = fmaxf(mt1, __shfl_xor_sync(0xffffffffu, mt1, off));
        }
        float mo0 = m_s[sr], mo1 = m_s[sr+1];
        float mn0 = fmaxf(mo0, mt0), mn1 = fmaxf(mo1, mt1);
        float p0[4], p1[4];
        float lt0 = 0.f, lt1 = 0.f;
#pragma unroll
        for (int j = 0; j < 4; j++) {
            p0[j] = __expf(s0[j] - mn0); lt0 += p0[j];
            p1[j] = __expf(s1[j] - mn1); lt1 += p1[j];
        }
#pragma unroll
        for (int off = 1; off < 8; off <<= 1) {
            lt0 += __shfl_xor_sync(0xffffffffu, lt0, off);
            lt1 += __shfl_xor_sync(0xffffffffu, lt1, off);
        }
        if ((tid & 7) == 0) {
            float al0 = __expf(mo0 - mn0);
            float al1 = __expf(mo1 - mn1);
            a_s[sr] = al0;  a_s[sr+1] = al1;
            m_s[sr] = mn0;  m_s[sr+1] = mn1;
            l_s[sr]   = l_s[sr]  *al0 + lt0;
            l_s[sr+1] = l_s[sr+1]*al1 + lt1;
        }
#pragma unroll
        for (int j = 0; j < 4; j++) {
            Sc[sr*33 + sc + j]     = p0[j];
            Sc[(sr+1)*33 + sc + j] = p1[j];
        }
        __syncthreads();

        // ---- O = O*alpha + P @ V ----
        float al0 = a_s[r0], al1 = a_s[r1];
#pragma unroll
        for (int u = 0; u < 4; u++) {
            o[0][u].x *= al0; o[0][u].y *= al0; o[0][u].z *= al0; o[0][u].w *= al0;
            o[1][u].x *= al1; o[1][u].y *= al1; o[1][u].z *= al1; o[1][u].w *= al1;
        }
#pragma unroll
        for (int j = 0; j < 32; j++) {
            float pa = Sc[r0*33 + j];
            float pb = Sc[r1*33 + j];
#pragma unroll
            for (int u = 0; u < 4; u++) {
                float4 vv = Vs4[j*32 + oc*4 + u];
                o[0][u].x = fmaf(pa, vv.x, o[0][u].x);
                o[0][u].y = fmaf(pa, vv.y, o[0][u].y);
                o[0][u].z = fmaf(pa, vv.z, o[0][u].z);
                o[0][u].w = fmaf(pa, vv.w, o[0][u].w);
                o[1][u].x = fmaf(pb, vv.x, o[1][u].x);
                o[1][u].y = fmaf(pb, vv.y, o[1][u].y);
                o[1][u].z = fmaf(pb, vv.z, o[1][u].z);
                o[1][u].w = fmaf(pb, vv.w, o[1][u].w);
            }
        }
        __syncthreads();
    }

    const float inv0 = 1.0f / l_s[r0];
    const float inv1 = 1.0f / l_s[r1];
    const int b = bh >> 4, h = bh & 15;
    float* out0 = ctx + ((size_t)b*S_ + qr0 + r0) * E_ + h*D_ + oc*16;
    float* out1 = ctx + ((size_t)b*S_ + qr0 + r1) * E_ + h*D_ + oc*16;
#pragma unroll
    for (int u = 0; u < 4; u++) {
        float4 v0 = o[0][u];
        v0.x *= inv0; v0.y *= inv0; v0.z *= inv0; v0.w *= inv0;
        *(float4*)(out0 + u*4) = v0;
        float4 v1 = o[1][u];
        v1.x *= inv1; v1.y *= inv1; v1.z *= inv1; v1.w *= inv1;
        *(float4*)(out1 + u*4) = v1;
    }
}

// ---------------------------------------------------------------------------
extern "C" void kernel_launch(void* const* d_in, const int* in_sizes, int n_in,
                              void* d_out, int out_size)
{
    const float* q  = (const float*)d_in[0];
    const float* k  = (const float*)d_in[1];
    const float* v  = (const float*)d_in[2];
    // d_in[3] = attn_mask (fixed causal -1e4 triu; applied analytically)
    const float* Wq = (const float*)d_in[4];
    const float* Wk = (const float*)d_in[5];
    const float* Wv = (const float*)d_in[6];
    const float* Wo = (const float*)d_in[7];
    float* out = (float*)d_out;

    float *Qp, *Kp, *Vp, *ctx;
    cudaGetSymbolAddress((void**)&Qp,  g_Qp);
    cudaGetSymbolAddress((void**)&Kp,  g_Kp);
    cudaGetSymbolAddress((void**)&Vp,  g_Vp);
    cudaGetSymbolAddress((void**)&ctx, g_ctx);

    cudaFuncSetAttribute(attn_kernel, cudaFuncAttributeMaxDynamicSharedMemorySize, ATTN_SMEM);

    const float qscale = 0.08838834764831845f;   // 1/sqrt(128)
    dim3 gg(N_/128, M_/128);   // (16, 32)

    gemm_xwT<<<gg, 256>>>(q, Wq, Qp, 1, qscale);
    gemm_xwT<<<gg, 256>>>(k, Wk, Kp, 1, 1.0f);
    gemm_xwT<<<gg, 256>>>(v, Wv, Vp, 1, 1.0f);

    attn_kernel<<<dim3(S_/64, B_*H_), 256, ATTN_SMEM>>>(Qp, Kp, Vp, ctx);

    gemm_xwT<<<gg, 256>>>(ctx, Wo, out, 0, 1.0f);
}

// round 5
// speedup vs baseline: 1.6557x; 1.6557x over previous
#include <cuda_runtime.h>
#include <cuda_bf16.h>
#include <math.h>
#include <cstdint>

static constexpr int B_ = 2, S_ = 2048, E_ = 2048, H_ = 16, D_ = 128;
static constexpr int M_ = B_ * S_;   // 4096
static constexpr int N_ = E_;        // 2048
static constexpr int K_ = E_;        // 2048

// ---------------- scratch (__device__ globals: allocation-free rule) --------
__device__ float g_Qp[B_*H_*S_*D_];
__device__ float g_Kp[B_*H_*S_*D_];
__device__ float g_Vp[B_*H_*S_*D_];
__device__ float g_ctx[B_*S_*E_];

__device__ __nv_bfloat16 g_qh[M_*K_], g_ql[M_*K_];
__device__ __nv_bfloat16 g_kh[M_*K_], g_kl[M_*K_];
__device__ __nv_bfloat16 g_vh[M_*K_], g_vl[M_*K_];
__device__ __nv_bfloat16 g_ch[M_*K_], g_cl[M_*K_];
__device__ __nv_bfloat16 g_wqh[N_*K_], g_wql[N_*K_];
__device__ __nv_bfloat16 g_wkh[N_*K_], g_wkl[N_*K_];
__device__ __nv_bfloat16 g_wvh[N_*K_], g_wvl[N_*K_];
__device__ __nv_bfloat16 g_woh[N_*K_], g_wol[N_*K_];

// ---------------- helpers ---------------------------------------------------
__device__ __forceinline__ uint32_t smem_u32(const void* p) {
    uint32_t a;
    asm("{ .reg .u64 t; cvta.to.shared.u64 t, %1; cvt.u32.u64 %0, t; }" : "=r"(a) : "l"(p));
    return a;
}

// ---------------- fp32 -> (hi, lo) bf16 split -------------------------------
__global__ __launch_bounds__(256)
void split_kernel(const float* __restrict__ x, __nv_bfloat16* __restrict__ hi,
                  __nv_bfloat16* __restrict__ lo, int n4)
{
    int i = blockIdx.x * 256 + threadIdx.x;
    if (i >= n4) return;
    float4 v = ((const float4*)x)[i];
    __nv_bfloat16 h0 = __float2bfloat16(v.x);
    __nv_bfloat16 h1 = __float2bfloat16(v.y);
    __nv_bfloat16 h2 = __float2bfloat16(v.z);
    __nv_bfloat16 h3 = __float2bfloat16(v.w);
    __nv_bfloat16 l0 = __float2bfloat16(v.x - __bfloat162float(h0));
    __nv_bfloat16 l1 = __float2bfloat16(v.y - __bfloat162float(h1));
    __nv_bfloat16 l2 = __float2bfloat16(v.z - __bfloat162float(h2));
    __nv_bfloat16 l3 = __float2bfloat16(v.w - __bfloat162float(h3));
    ((__nv_bfloat162*)hi)[i*2]   = __halves2bfloat162(h0, h1);
    ((__nv_bfloat162*)hi)[i*2+1] = __halves2bfloat162(h2, h3);
    ((__nv_bfloat162*)lo)[i*2]   = __halves2bfloat162(l0, l1);
    ((__nv_bfloat162*)lo)[i*2+1] = __halves2bfloat162(l2, l3);
}

// ---------------- HMMA GEMM: C = A @ W^T (3-pass bf16 split) ----------------
// 128x128 tile, BK=32, 256 threads (8 warps of 32x64), mma.sync m16n8k16.
// smem: A tiles [2][128][32] bf16 @ 0, B tiles [2][128][32] bf16 @ 16384.
// Swizzle: byte = row*64 + ((seg ^ ((row>>1)&3))<<4), seg = k16B-segment (0..3).

__device__ __forceinline__ void ldmx4(uint32_t* r, uint32_t addr) {
    asm volatile("ldmatrix.sync.aligned.m8n8.x4.shared.b16 {%0,%1,%2,%3}, [%4];"
        : "=r"(r[0]), "=r"(r[1]), "=r"(r[2]), "=r"(r[3]) : "r"(addr));
}
__device__ __forceinline__ void mma16816(float* c, const uint32_t* a, uint32_t b0, uint32_t b1) {
    asm volatile("mma.sync.aligned.m16n8k16.row.col.f32.bf16.bf16.f32 "
        "{%0,%1,%2,%3}, {%4,%5,%6,%7}, {%8,%9}, {%0,%1,%2,%3};"
        : "+f"(c[0]), "+f"(c[1]), "+f"(c[2]), "+f"(c[3])
        : "r"(a[0]), "r"(a[1]), "r"(a[2]), "r"(a[3]), "r"(b0), "r"(b1));
}

__global__ __launch_bounds__(256, 2)
void gemm_hmma(const __nv_bfloat16* __restrict__ Ah, const __nv_bfloat16* __restrict__ Al,
               const __nv_bfloat16* __restrict__ Wh, const __nv_bfloat16* __restrict__ Wl,
               float* __restrict__ C, int split, float scale)
{
    __shared__ __align__(16) char sm[32768];
    const uint32_t sbase = smem_u32(sm);
    const int tid  = threadIdx.x;
    const int lane = tid & 31, wid = tid >> 5;
    const int wm = wid & 3, wn = wid >> 2;       // warp tile: rows 32*wm, cols 64*wn
    const int m0 = blockIdx.y * 128;
    const int n0 = blockIdx.x * 128;

    float acc[2][8][4];
#pragma unroll
    for (int i = 0; i < 2; i++)
#pragma unroll
        for (int j = 0; j < 8; j++)
#pragma unroll
            for (int t = 0; t < 4; t++) acc[i][j][t] = 0.f;

    // per-thread cp.async slots: idx in {tid, tid+256}; row = idx>>2, seg = idx&3
    const int r0i = tid >> 2, s0i = tid & 3;
    const int r1i = (tid + 256) >> 2, s1i = s0i;
    const uint32_t off0 = (uint32_t)r0i * 64u + (uint32_t)((s0i ^ ((r0i >> 1) & 3)) << 4);
    const uint32_t off1 = (uint32_t)r1i * 64u + (uint32_t)((s1i ^ ((r1i >> 1) & 3)) << 4);

    const int NITER = 192;   // 3 passes x 64 iters of BK=32

    // precomputed ldmatrix address components
    const int rowA0 = wm * 32 + (lane & 7) + (lane & 8);           // mt adds 16
    const int aseg  = (lane >> 4);                                  // + s0
    const int rowB0 = wn * 64 + (lane & 7) + ((lane >> 4) << 3);   // ng adds 16
    const int bseg  = (lane >> 3) & 1;                              // + s0

#define ISSUE_TILE(it) do { \
        int pass_ = (it) >> 6; int kb_ = ((it) & 63) << 5; \
        const __nv_bfloat16* Ap_ = (pass_ == 2) ? Al : Ah; \
        const __nv_bfloat16* Wp_ = (pass_ == 1) ? Wl : Wh; \
        uint32_t ab_ = sbase + (((it) & 1) << 13); \
        uint32_t bb_ = sbase + 16384u + (((it) & 1) << 13); \
        const void* ga0 = Ap_ + (size_t)(m0 + r0i) * K_ + kb_ + s0i * 8; \
        const void* ga1 = Ap_ + (size_t)(m0 + r1i) * K_ + kb_ + s1i * 8; \
        const void* gb0 = Wp_ + (size_t)(n0 + r0i) * K_ + kb_ + s0i * 8; \
        const void* gb1 = Wp_ + (size_t)(n0 + r1i) * K_ + kb_ + s1i * 8; \
        asm volatile("cp.async.cg.shared.global [%0], [%1], 16;" :: "r"(ab_ + off0), "l"(ga0)); \
        asm volatile("cp.async.cg.shared.global [%0], [%1], 16;" :: "r"(ab_ + off1), "l"(ga1)); \
        asm volatile("cp.async.cg.shared.global [%0], [%1], 16;" :: "r"(bb_ + off0), "l"(gb0)); \
        asm volatile("cp.async.cg.shared.global [%0], [%1], 16;" :: "r"(bb_ + off1), "l"(gb1)); \
        asm volatile("cp.async.commit_group;"); \
    } while (0)

    ISSUE_TILE(0);

    for (int iter = 0; iter < NITER; iter++) {
        asm volatile("cp.async.wait_group 0;" ::: "memory");
        __syncthreads();
        if (iter + 1 < NITER) ISSUE_TILE(iter + 1);

        const uint32_t abase = sbase + ((iter & 1) << 13);
        const uint32_t bbase = sbase + 16384u + ((iter & 1) << 13);

#pragma unroll
        for (int ks = 0; ks < 2; ks++) {
            const int s0 = ks * 2;
            uint32_t a[2][4];
#pragma unroll
            for (int mt = 0; mt < 2; mt++) {
                int row = rowA0 + mt * 16;
                int sl = s0 + aseg;
                uint32_t addr = abase + (uint32_t)row * 64u + (uint32_t)((sl ^ ((row >> 1) & 3)) << 4);
                ldmx4(a[mt], addr);
            }
#pragma unroll
            for (int ng = 0; ng < 4; ng++) {
                int row = rowB0 + ng * 16;
                int sl = s0 + bseg;
                uint32_t addr = bbase + (uint32_t)row * 64u + (uint32_t)((sl ^ ((row >> 1) & 3)) << 4);
                uint32_t b[4];
                ldmx4(b, addr);
#pragma unroll
                for (int mt = 0; mt < 2; mt++) {
                    mma16816(acc[mt][2*ng],   a[mt], b[0], b[1]);
                    mma16816(acc[mt][2*ng+1], a[mt], b[2], b[3]);
                }
            }
        }
    }

    // ---- epilogue ----
    const int crow = (lane >> 2);
    const int ccol = (lane & 3) * 2;
#pragma unroll
    for (int mt = 0; mt < 2; mt++) {
#pragma unroll
        for (int half = 0; half < 2; half++) {
            int m = m0 + wm * 32 + mt * 16 + crow + half * 8;
            float* outr;
            if (split) {
                int b = m >> 11, s = m & (S_ - 1);
                int h = blockIdx.x;
                outr = C + (((size_t)(b * H_ + h)) * S_ + s) * (size_t)D_;
            } else {
                outr = C + (size_t)m * N_ + n0;
            }
#pragma unroll
            for (int nt = 0; nt < 8; nt++) {
                int c = wn * 64 + nt * 8 + ccol;
                float2 v;
                v.x = acc[mt][nt][half*2 + 0] * scale;
                v.y = acc[mt][nt][half*2 + 1] * scale;
                *(float2*)(outr + c) = v;
            }
        }
    }
#undef ISSUE_TILE
}

// ---------------------------------------------------------------------------
// Flash attention (FFMA; unchanged — next round's target)
// ---------------------------------------------------------------------------
static constexpr int ATTN_SMEM = (64*128 + 32*128 + 32*128 + 64*33 + 3*64) * 4;

__device__ __forceinline__ float dot4(float4 a, float4 b, float acc) {
    acc = fmaf(a.x, b.x, acc);
    acc = fmaf(a.y, b.y, acc);
    acc = fmaf(a.z, b.z, acc);
    acc = fmaf(a.w, b.w, acc);
    return acc;
}

__global__ __launch_bounds__(256)
void attn_kernel(const float* __restrict__ Qp, const float* __restrict__ Kp,
                 const float* __restrict__ Vp, float* __restrict__ ctx)
{
    extern __shared__ float smf[];
    float4* Qs4 = (float4*)smf;
    float4* Ks4 = Qs4 + 64*32;
    float4* Vs4 = Ks4 + 32*32;
    float*  Sc  = (float*)(Vs4 + 32*32);
    float*  m_s = Sc + 64*33;
    float*  l_s = m_s + 64;
    float*  a_s = l_s + 64;

    const int tid = threadIdx.x;
    const int qt  = blockIdx.x;
    const int bh  = blockIdx.y;
    const int qr0 = qt * 64;

    if (tid < 64) { m_s[tid] = -1e30f; l_s[tid] = 0.f; }

    const float4* Qg = (const float4*)(Qp + ((size_t)bh * S_ + qr0) * D_);
#pragma unroll
    for (int r = 0; r < 8; r++) {
        int idx = tid + 256*r;
        int row = idx >> 5, c4 = idx & 31;
        Qs4[row*32 + ((c4 + (row >> 1)) & 31)] = Qg[idx];
    }

    const int sr = (tid >> 3) * 2;
    const int sc = (tid & 7) * 4;
    const int qoff = sr >> 1;
    const int koff = sc >> 2;
    const int qrow0 = qr0 + sr;
    const int qrow1 = qrow0 + 1;

    const int r0 = tid & 31, r1 = r0 + 32;
    const int oc = tid >> 5;
    float4 o[2][4];
#pragma unroll
    for (int a = 0; a < 2; a++)
#pragma unroll
        for (int u = 0; u < 4; u++) o[a][u] = make_float4(0.f, 0.f, 0.f, 0.f);

    __syncthreads();

    const int nkt = 2*qt + 2;
    for (int kt = 0; kt < nkt; kt++) {
        const int k0 = kt * 32;
        const float4* Kg = (const float4*)(Kp + ((size_t)bh * S_ + k0) * D_);
        const float4* Vg = (const float4*)(Vp + ((size_t)bh * S_ + k0) * D_);
#pragma unroll
        for (int r = 0; r < 4; r++) {
            int idx = tid + 256*r;
            int row = idx >> 5, c4 = idx & 31;
            Ks4[row*32 + ((c4 + (row >> 2)) & 31)] = Kg[idx];
            Vs4[idx] = Vg[idx];
        }
        __syncthreads();

        float s0[4] = {0,0,0,0}, s1[4] = {0,0,0,0};
#pragma unroll
        for (int c4 = 0; c4 < 32; c4++) {
            int qp = (c4 + qoff) & 31;
            int kp = (c4 + koff) & 31;
            float4 qa  = Qs4[sr*32 + qp];
            float4 qb  = Qs4[(sr+1)*32 + qp];
            float4 k0v = Ks4[(sc+0)*32 + kp];
            float4 k1v = Ks4[(sc+1)*32 + kp];
            float4 k2v = Ks4[(sc+2)*32 + kp];
            float4 k3v = Ks4[(sc+3)*32 + kp];
            s0[0] = dot4(qa, k0v, s0[0]);
            s0[1] = dot4(qa, k1v, s0[1]);
            s0[2] = dot4(qa, k2v, s0[2]);
            s0[3] = dot4(qa, k3v, s0[3]);
            s1[0] = dot4(qb, k0v, s1[0]);
            s1[1] = dot4(qb, k1v, s1[1]);
            s1[2] = dot4(qb, k2v, s1[2]);
            s1[3] = dot4(qb, k3v, s1[3]);
        }

#pragma unroll
        for (int j = 0; j < 4; j++) {
            int kc = k0 + sc + j;
            if (kc > qrow0) s0[j] = -1e30f;
            if (kc > qrow1) s1[j] = -1e30f;
        }

        float mt0 = fmaxf(fmaxf(s0[0], s0[1]), fmaxf(s0[2], s0[3]));
        float mt1 = fmaxf(fmaxf(s1[0], s1[1]), fmaxf(s1[2], s1[3]));
#pragma unroll
        for (int off = 1; off < 8; off <<= 1) {
            mt0 = fmaxf(mt0, __shfl_xor_sync(0xffffffffu, mt0, off));
            mt1 = fmaxf(mt1, __shfl_xor_sync(0xffffffffu, mt1, off));
        }
        float mo0 = m_s[sr], mo1 = m_s[sr+1];
        float mn0 = fmaxf(mo0, mt0), mn1 = fmaxf(mo1, mt1);
        float p0[4], p1[4];
        float lt0 = 0.f, lt1 = 0.f;
#pragma unroll
        for (int j = 0; j < 4; j++) {
            p0[j] = __expf(s0[j] - mn0); lt0 += p0[j];
            p1[j] = __expf(s1[j] - mn1); lt1 += p1[j];
        }
#pragma unroll
        for (int off = 1; off < 8; off <<= 1) {
            lt0 += __shfl_xor_sync(0xffffffffu, lt0, off);
            lt1 += __shfl_xor_sync(0xffffffffu, lt1, off);
        }
        if ((tid & 7) == 0) {
            float al0 = __expf(mo0 - mn0);
            float al1 = __expf(mo1 - mn1);
            a_s[sr] = al0;  a_s[sr+1] = al1;
            m_s[sr] = mn0;  m_s[sr+1] = mn1;
            l_s[sr]   = l_s[sr]  *al0 + lt0;
            l_s[sr+1] = l_s[sr+1]*al1 + lt1;
        }
#pragma unroll
        for (int j = 0; j < 4; j++) {
            Sc[sr*33 + sc + j]     = p0[j];
            Sc[(sr+1)*33 + sc + j] = p1[j];
        }
        __syncthreads();

        float al0 = a_s[r0], al1 = a_s[r1];
#pragma unroll
        for (int u = 0; u < 4; u++) {
            o[0][u].x *= al0; o[0][u].y *= al0; o[0][u].z *= al0; o[0][u].w *= al0;
            o[1][u].x *= al1; o[1][u].y *= al1; o[1][u].z *= al1; o[1][u].w *= al1;
        }
#pragma unroll
        for (int j = 0; j < 32; j++) {
            float pa = Sc[r0*33 + j];
            float pb = Sc[r1*33 + j];
#pragma unroll
            for (int u = 0; u < 4; u++) {
                float4 vv = Vs4[j*32 + oc*4 + u];
                o[0][u].x = fmaf(pa, vv.x, o[0][u].x);
                o[0][u].y = fmaf(pa, vv.y, o[0][u].y);
                o[0][u].z = fmaf(pa, vv.z, o[0][u].z);
                o[0][u].w = fmaf(pa, vv.w, o[0][u].w);
                o[1][u].x = fmaf(pb, vv.x, o[1][u].x);
                o[1][u].y = fmaf(pb, vv.y, o[1][u].y);
                o[1][u].z = fmaf(pb, vv.z, o[1][u].z);
                o[1][u].w = fmaf(pb, vv.w, o[1][u].w);
            }
        }
        __syncthreads();
    }

    const float inv0 = 1.0f / l_s[r0];
    const float inv1 = 1.0f / l_s[r1];
    const int b = bh >> 4, h = bh & 15;
    float* out0 = ctx + ((size_t)b*S_ + qr0 + r0) * E_ + h*D_ + oc*16;
    float* out1 = ctx + ((size_t)b*S_ + qr0 + r1) * E_ + h*D_ + oc*16;
#pragma unroll
    for (int u = 0; u < 4; u++) {
        float4 v0 = o[0][u];
        v0.x *= inv0; v0.y *= inv0; v0.z *= inv0; v0.w *= inv0;
        *(float4*)(out0 + u*4) = v0;
        float4 v1 = o[1][u];
        v1.x *= inv1; v1.y *= inv1; v1.z *= inv1; v1.w *= inv1;
        *(float4*)(out1 + u*4) = v1;
    }
}

// ---------------------------------------------------------------------------
extern "C" void kernel_launch(void* const* d_in, const int* in_sizes, int n_in,
                              void* d_out, int out_size)
{
    const float* q  = (const float*)d_in[0];
    const float* k  = (const float*)d_in[1];
    const float* v  = (const float*)d_in[2];
    const float* Wq = (const float*)d_in[4];
    const float* Wk = (const float*)d_in[5];
    const float* Wv = (const float*)d_in[6];
    const float* Wo = (const float*)d_in[7];
    float* out = (float*)d_out;

    float *Qp, *Kp, *Vp, *ctx;
    cudaGetSymbolAddress((void**)&Qp,  g_Qp);
    cudaGetSymbolAddress((void**)&Kp,  g_Kp);
    cudaGetSymbolAddress((void**)&Vp,  g_Vp);
    cudaGetSymbolAddress((void**)&ctx, g_ctx);

    __nv_bfloat16 *qh,*ql,*kh,*kl,*vh,*vl,*ch,*cl;
    __nv_bfloat16 *wqh,*wql,*wkh,*wkl,*wvh,*wvl,*woh,*wol;
    cudaGetSymbolAddress((void**)&qh, g_qh);  cudaGetSymbolAddress((void**)&ql, g_ql);
    cudaGetSymbolAddress((void**)&kh, g_kh);  cudaGetSymbolAddress((void**)&kl, g_kl);
    cudaGetSymbolAddress((void**)&vh, g_vh);  cudaGetSymbolAddress((void**)&vl, g_vl);
    cudaGetSymbolAddress((void**)&ch, g_ch);  cudaGetSymbolAddress((void**)&cl, g_cl);
    cudaGetSymbolAddress((void**)&wqh, g_wqh); cudaGetSymbolAddress((void**)&wql, g_wql);
    cudaGetSymbolAddress((void**)&wkh, g_wkh); cudaGetSymbolAddress((void**)&wkl, g_wkl);
    cudaGetSymbolAddress((void**)&wvh, g_wvh); cudaGetSymbolAddress((void**)&wvl, g_wvl);
    cudaGetSymbolAddress((void**)&woh, g_woh); cudaGetSymbolAddress((void**)&wol, g_wol);

    cudaFuncSetAttribute(attn_kernel, cudaFuncAttributeMaxDynamicSharedMemorySize, ATTN_SMEM);

    const int nx4 = M_ * K_ / 4;   // activations: 4096x2048
    const int nw4 = N_ * K_ / 4;   // weights: 2048x2048

    split_kernel<<<nx4/256, 256>>>(q, qh, ql, nx4);
    split_kernel<<<nx4/256, 256>>>(k, kh, kl, nx4);
    split_kernel<<<nx4/256, 256>>>(v, vh, vl, nx4);
    split_kernel<<<nw4/256, 256>>>(Wq, wqh, wql, nw4);
    split_kernel<<<nw4/256, 256>>>(Wk, wkh, wkl, nw4);
    split_kernel<<<nw4/256, 256>>>(Wv, wvh, wvl, nw4);
    split_kernel<<<nw4/256, 256>>>(Wo, woh, wol, nw4);

    const float qscale = 0.08838834764831845f;   // 1/sqrt(128)
    dim3 gg(N_/128, M_/128);   // (16, 32)

    gemm_hmma<<<gg, 256>>>(qh, ql, wqh, wql, Qp, 1, qscale);
    gemm_hmma<<<gg, 256>>>(kh, kl, wkh, wkl, Kp, 1, 1.0f);
    gemm_hmma<<<gg, 256>>>(vh, vl, wvh, wvl, Vp, 1, 1.0f);

    attn_kernel<<<dim3(S_/64, B_*H_), 256, ATTN_SMEM>>>(Qp, Kp, Vp, ctx);

    split_kernel<<<nx4/256, 256>>>(ctx, ch, cl, nx4);

    gemm_hmma<<<gg, 256>>>(ch, cl, woh, wol, out, 0, 1.0f);
}

// round 8
// speedup vs baseline: 2.7912x; 1.6858x over previous
#include <cuda_runtime.h>
#include <cuda_bf16.h>
#include <math.h>
#include <cstdint>

static constexpr int B_ = 2, S_ = 2048, E_ = 2048, H_ = 16, D_ = 128;
static constexpr int M_ = B_ * S_;   // 4096
static constexpr int N_ = E_;        // 2048
static constexpr int K_ = E_;        // 2048

// ---------------- scratch (__device__ globals: allocation-free rule) --------
__device__ __nv_bfloat16 g_qh[M_*K_], g_ql[M_*K_];
__device__ __nv_bfloat16 g_kh[M_*K_], g_kl[M_*K_];
__device__ __nv_bfloat16 g_vh[M_*K_], g_vl[M_*K_];
__device__ __nv_bfloat16 g_wqh[N_*K_], g_wql[N_*K_];
__device__ __nv_bfloat16 g_wkh[N_*K_], g_wkl[N_*K_];
__device__ __nv_bfloat16 g_wvh[N_*K_], g_wvl[N_*K_];
__device__ __nv_bfloat16 g_woh[N_*K_], g_wol[N_*K_];
// projections, head-split [B][H][S][D], hi/lo
__device__ __nv_bfloat16 g_Qh[B_*H_*S_*D_], g_Ql[B_*H_*S_*D_];
__device__ __nv_bfloat16 g_Kh[B_*H_*S_*D_], g_Kl[B_*H_*S_*D_];
__device__ __nv_bfloat16 g_Vh[B_*H_*S_*D_], g_Vl[B_*H_*S_*D_];
// attention output, [m][e] hi/lo
__device__ __nv_bfloat16 g_ch[M_*E_], g_cl[M_*E_];

// ---------------- helpers ---------------------------------------------------
__device__ __forceinline__ uint32_t smem_u32(const void* p) {
    uint32_t a;
    asm("{ .reg .u64 t; cvta.to.shared.u64 t, %1; cvt.u32.u64 %0, t; }" : "=r"(a) : "l"(p));
    return a;
}
__device__ __forceinline__ void ldmx4(uint32_t* r, uint32_t addr) {
    asm volatile("ldmatrix.sync.aligned.m8n8.x4.shared.b16 {%0,%1,%2,%3}, [%4];"
        : "=r"(r[0]), "=r"(r[1]), "=r"(r[2]), "=r"(r[3]) : "r"(addr));
}
__device__ __forceinline__ void ldmx4t(uint32_t* r, uint32_t addr) {
    asm volatile("ldmatrix.sync.aligned.m8n8.x4.trans.shared.b16 {%0,%1,%2,%3}, [%4];"
        : "=r"(r[0]), "=r"(r[1]), "=r"(r[2]), "=r"(r[3]) : "r"(addr));
}
__device__ __forceinline__ void mma16816(float* c, const uint32_t* a, uint32_t b0, uint32_t b1) {
    asm volatile("mma.sync.aligned.m16n8k16.row.col.f32.bf16.bf16.f32 "
        "{%0,%1,%2,%3}, {%4,%5,%6,%7}, {%8,%9}, {%0,%1,%2,%3};"
        : "+f"(c[0]), "+f"(c[1]), "+f"(c[2]), "+f"(c[3])
        : "r"(a[0]), "r"(a[1]), "r"(a[2]), "r"(a[3]), "r"(b0), "r"(b1));
}
__device__ __forceinline__ uint32_t pack_bf16x2(float lo, float hi) {
    uint32_t d;
    asm("cvt.rn.bf16x2.f32 %0, %1, %2;" : "=r"(d) : "f"(hi), "f"(lo));
    return d;
}
// fast exp2 on the FMA pipe (no MUFU). t <= 0 expected; clamped at -80.
__device__ __forceinline__ float fexp2(float t) {
    t = fmaxf(t, -80.0f);
    float r  = __fadd_rn(t, 12582912.0f);         // 1.5*2^23 magic round
    int   i  = __float_as_int(r) - 0x4B400000;
    float rf = __fadd_rn(r, -12582912.0f);
    float f  = __fadd_rn(t, -rf);                 // f in [-0.5, 0.5]
    float p  = 0.0013333558f;
    p = fmaf(p, f, 0.0096181291f);
    p = fmaf(p, f, 0.0555041087f);
    p = fmaf(p, f, 0.2402265069f);
    p = fmaf(p, f, 0.6931471806f);
    p = fmaf(p, f, 1.0f);
    return __int_as_float(__float_as_int(p) + (i << 23));
}

// ---------------- fp32 -> (hi, lo) bf16 split -------------------------------
__global__ __launch_bounds__(256)
void split_kernel(const float* __restrict__ x, __nv_bfloat16* __restrict__ hi,
                  __nv_bfloat16* __restrict__ lo, int n4)
{
    int i = blockIdx.x * 256 + threadIdx.x;
    if (i >= n4) return;
    float4 v = ((const float4*)x)[i];
    __nv_bfloat16 h0 = __float2bfloat16(v.x);
    __nv_bfloat16 h1 = __float2bfloat16(v.y);
    __nv_bfloat16 h2 = __float2bfloat16(v.z);
    __nv_bfloat16 h3 = __float2bfloat16(v.w);
    __nv_bfloat16 l0 = __float2bfloat16(v.x - __bfloat162float(h0));
    __nv_bfloat16 l1 = __float2bfloat16(v.y - __bfloat162float(h1));
    __nv_bfloat16 l2 = __float2bfloat16(v.z - __bfloat162float(h2));
    __nv_bfloat16 l3 = __float2bfloat16(v.w - __bfloat162float(h3));
    ((__nv_bfloat162*)hi)[i*2]   = __halves2bfloat162(h0, h1);
    ((__nv_bfloat162*)hi)[i*2+1] = __halves2bfloat162(h2, h3);
    ((__nv_bfloat162*)lo)[i*2]   = __halves2bfloat162(l0, l1);
    ((__nv_bfloat162*)lo)[i*2+1] = __halves2bfloat162(l2, l3);
}

// ---------------- HMMA GEMM: C = A @ W^T (3-pass bf16 split) ----------------
// 128x128 tile, BK=32, 128 threads (4 warps of 64x64), 4-stage cp.async.
static constexpr int GEMM_SMEM = 4 * 16384;   // 65536

__global__ __launch_bounds__(128, 2)
void gemm_hmma(const __nv_bfloat16* __restrict__ Ah, const __nv_bfloat16* __restrict__ Al,
               const __nv_bfloat16* __restrict__ Wh, const __nv_bfloat16* __restrict__ Wl,
               float* __restrict__ Cf, __nv_bfloat16* __restrict__ Chi,
               __nv_bfloat16* __restrict__ Clo, int mode, float scale)
{
    extern __shared__ char sm[];
    const uint32_t sbase = smem_u32(sm);
    const int tid  = threadIdx.x;
    const int lane = tid & 31, wid = tid >> 5;
    const int wm = wid & 1, wn = wid >> 1;       // warp tile: rows 64*wm, cols 64*wn
    const int m0 = blockIdx.y * 128;
    const int n0 = blockIdx.x * 128;

    float acc[4][8][4];
#pragma unroll
    for (int i = 0; i < 4; i++)
#pragma unroll
        for (int j = 0; j < 8; j++)
#pragma unroll
            for (int t = 0; t < 4; t++) acc[i][j][t] = 0.f;

    const int crow = tid >> 2, cseg = tid & 3;

    const int NITER = 192;   // 3 passes x 64 k-iters of BK=32

#define G_ISSUE(it) do { \
        int pass_ = (it) >> 6; int kb_ = ((it) & 63) << 5; \
        const __nv_bfloat16* Ap_ = (pass_ == 2) ? Al : Ah; \
        const __nv_bfloat16* Wp_ = (pass_ == 1) ? Wl : Wh; \
        uint32_t st_ = sbase + (uint32_t)(((it) & 3) * 16384); \
        _Pragma("unroll") \
        for (int j_ = 0; j_ < 4; j_++) { \
            int row_ = crow + j_ * 32; \
            uint32_t off_ = (uint32_t)row_ * 64u + (uint32_t)((cseg ^ ((row_ >> 1) & 3)) << 4); \
            const void* ga_ = Ap_ + (size_t)(m0 + row_) * K_ + kb_ + cseg * 8; \
            const void* gb_ = Wp_ + (size_t)(n0 + row_) * K_ + kb_ + cseg * 8; \
            asm volatile("cp.async.cg.shared.global [%0], [%1], 16;" :: "r"(st_ + off_), "l"(ga_)); \
            asm volatile("cp.async.cg.shared.global [%0], [%1], 16;" :: "r"(st_ + 8192u + off_), "l"(gb_)); \
        } \
        asm volatile("cp.async.commit_group;"); \
    } while (0)

    G_ISSUE(0); G_ISSUE(1); G_ISSUE(2);

    const int rowA0 = wm * 64 + (lane & 7) + (lane & 8);
    const int asegb = (lane >> 4);
    const int rowB0 = wn * 64 + (lane & 7) + ((lane >> 4) << 3);
    const int bsegb = (lane >> 3) & 1;

    for (int it = 0; it < NITER; it++) {
        if (it < NITER - 2)      { asm volatile("cp.async.wait_group 2;" ::: "memory"); }
        else if (it == NITER - 2){ asm volatile("cp.async.wait_group 1;" ::: "memory"); }
        else                     { asm volatile("cp.async.wait_group 0;" ::: "memory"); }
        __syncthreads();
        if (it + 3 < NITER) G_ISSUE(it + 3);

        const uint32_t ab = sbase + (uint32_t)((it & 3) * 16384);
        const uint32_t bb = ab + 8192u;

#pragma unroll
        for (int ks = 0; ks < 2; ks++) {
            uint32_t a[4][4];
#pragma unroll
            for (int mt = 0; mt < 4; mt++) {
                int row = rowA0 + mt * 16;
                int sl = ks * 2 + asegb;
                ldmx4(a[mt], ab + (uint32_t)row * 64u + (uint32_t)((sl ^ ((row >> 1) & 3)) << 4));
            }
#pragma unroll
            for (int nb = 0; nb < 4; nb++) {
                int row = rowB0 + nb * 16;
                int sl = ks * 2 + bsegb;
                uint32_t b[4];
                ldmx4(b, bb + (uint32_t)row * 64u + (uint32_t)((sl ^ ((row >> 1) & 3)) << 4));
#pragma unroll
                for (int mt = 0; mt < 4; mt++) {
                    mma16816(acc[mt][2*nb],   a[mt], b[0], b[1]);
                    mma16816(acc[mt][2*nb+1], a[mt], b[2], b[3]);
                }
            }
        }
    }
#undef G_ISSUE

    // ---- epilogue ----
#pragma unroll
    for (int mt = 0; mt < 4; mt++) {
#pragma unroll
        for (int half = 0; half < 2; half++) {
            int m = m0 + wm * 64 + mt * 16 + (lane >> 2) + half * 8;
            if (mode == 1) {
                int b = m >> 11, s = m & (S_ - 1);
                int h = blockIdx.x;
                size_t base = (((size_t)(b * H_ + h)) * S_ + s) * (size_t)D_;
#pragma unroll
                for (int n8 = 0; n8 < 8; n8++) {
                    int c = wn * 64 + n8 * 8 + 2 * (lane & 3);
                    float v0 = acc[mt][n8][half*2]   * scale;
                    float v1 = acc[mt][n8][half*2+1] * scale;
                    __nv_bfloat16 h0 = __float2bfloat16(v0);
                    __nv_bfloat16 h1 = __float2bfloat16(v1);
                    __nv_bfloat16 l0 = __float2bfloat16(v0 - __bfloat162float(h0));
                    __nv_bfloat16 l1 = __float2bfloat16(v1 - __bfloat162float(h1));
                    *(__nv_bfloat162*)(Chi + base + c) = __halves2bfloat162(h0, h1);
                    *(__nv_bfloat162*)(Clo + base + c) = __halves2bfloat162(l0, l1);
                }
            } else {
#pragma unroll
                for (int n8 = 0; n8 < 8; n8++) {
                    int c = wn * 64 + n8 * 8 + 2 * (lane & 3);
                    float2 v;
                    v.x = acc[mt][n8][half*2];
                    v.y = acc[mt][n8][half*2+1];
                    *(float2*)(Cf + (size_t)m * N_ + n0 + c) = v;
                }
            }
        }
    }
}

// ---------------- HMMA flash attention --------------------------------------
// CTA: 128 threads (4 warps), Br=128, Bc=64, D=128.
// Scores 3-pass hi/lo; P hi/lo; PV 3-pass (Ph*Vh + Pl*Vh + Ph*Vl).
static constexpr int AT_QH  = 0;
static constexpr int AT_QL  = 34816;
static constexpr int AT_KV0 = 69632;       // stage stride 69632
static constexpr int AT_KH = 0, AT_KL = 17408, AT_VH = 34816, AT_VL = 52224;
static constexpr int ATTN_SMEM = AT_KV0 + 2 * 69632;   // 208896

__device__ __forceinline__ void attn_issue_kv(
    uint32_t sb, int stage, int bh, int kv0, int tid,
    const __nv_bfloat16* Kh, const __nv_bfloat16* Kl,
    const __nv_bfloat16* Vh, const __nv_bfloat16* Vl)
{
    uint32_t kb = sb + AT_KV0 + (uint32_t)(stage * 69632);
    const __nv_bfloat16* srcs[4] = {Kh, Kl, Vh, Vl};
    const uint32_t offs[4] = {AT_KH, AT_KL, AT_VH, AT_VL};
#pragma unroll
    for (int m = 0; m < 4; m++) {
        const __nv_bfloat16* src = srcs[m] + ((size_t)bh * S_ + kv0) * D_;
#pragma unroll
        for (int j = 0; j < 8; j++) {
            int idx = tid + j * 128;
            int row = idx >> 4, seg = idx & 15;
            const void* g = src + (size_t)row * D_ + seg * 8;
            asm volatile("cp.async.cg.shared.global [%0], [%1], 16;"
                :: "r"(kb + offs[m] + (uint32_t)(row * 272 + seg * 16)), "l"(g));
        }
    }
    asm volatile("cp.async.commit_group;");
}

__global__ __launch_bounds__(128)
void attn_hmma(const __nv_bfloat16* __restrict__ Qh, const __nv_bfloat16* __restrict__ Ql,
               const __nv_bfloat16* __restrict__ Kh, const __nv_bfloat16* __restrict__ Kl,
               const __nv_bfloat16* __restrict__ Vh, const __nv_bfloat16* __restrict__ Vl,
               __nv_bfloat16* __restrict__ Chi, __nv_bfloat16* __restrict__ Clo)
{
    extern __shared__ char sm[];
    const uint32_t sb = smem_u32(sm);
    const int tid = threadIdx.x;
    const int lane = tid & 31, wid = tid >> 5;
    const int qt = (int)gridDim.x - 1 - (int)blockIdx.x;   // heavy tiles first
    const int bh = blockIdx.y;
    const int q0 = qt * 128;
    const int nt = 2 * qt + 2;

    // ---- load Q (hi+lo) as its own cp.async group ----
    {
        const __nv_bfloat16* qsrc[2] = {Qh + ((size_t)bh * S_ + q0) * D_,
                                        Ql + ((size_t)bh * S_ + q0) * D_};
        const uint32_t qoff[2] = {AT_QH, AT_QL};
#pragma unroll
        for (int m = 0; m < 2; m++) {
#pragma unroll
            for (int j = 0; j < 16; j++) {
                int idx = tid + j * 128;
                int row = idx >> 4, seg = idx & 15;
                const void* g = qsrc[m] + (size_t)row * D_ + seg * 8;
                asm volatile("cp.async.cg.shared.global [%0], [%1], 16;"
                    :: "r"(sb + qoff[m] + (uint32_t)(row * 272 + seg * 16)), "l"(g));
            }
        }
        asm volatile("cp.async.commit_group;");
    }
    attn_issue_kv(sb, 0, bh, 0, tid, Kh, Kl, Vh, Vl);
    if (nt > 1) attn_issue_kv(sb, 1, bh, 64, tid, Kh, Kl, Vh, Vl);

    float oacc[2][16][4];
#pragma unroll
    for (int mt = 0; mt < 2; mt++)
#pragma unroll
        for (int n = 0; n < 16; n++)
#pragma unroll
            for (int t = 0; t < 4; t++) oacc[mt][n][t] = 0.f;
    float mrow[2][2] = {{-1e30f, -1e30f}, {-1e30f, -1e30f}};
    float lrow[2][2] = {{0.f, 0.f}, {0.f, 0.f}};

    for (int kt = 0; kt < nt; kt++) {
        const int kv0 = kt * 64;
        if (kt + 1 < nt) { asm volatile("cp.async.wait_group 1;" ::: "memory"); }
        else             { asm volatile("cp.async.wait_group 0;" ::: "memory"); }
        __syncthreads();
        const uint32_t kb = sb + AT_KV0 + (uint32_t)((kt & 1) * 69632);

        // ---- scores: S = Qh*Kh^T + Qh*Kl^T + Ql*Kh^T ----
        float sacc[2][8][4];
#pragma unroll
        for (int mt = 0; mt < 2; mt++)
#pragma unroll
            for (int j = 0; j < 8; j++)
#pragma unroll
                for (int t = 0; t < 4; t++) sacc[mt][j][t] = 0.f;

#pragma unroll
        for (int ks = 0; ks < 8; ks++) {
            uint32_t qa_h[2][4], qa_l[2][4];
#pragma unroll
            for (int mt = 0; mt < 2; mt++) {
                int row = wid * 32 + mt * 16 + (lane & 7) + (lane & 8);
                int seg = ks * 2 + (lane >> 4);
                ldmx4(qa_h[mt], sb + AT_QH + (uint32_t)(row * 272 + seg * 16));
                ldmx4(qa_l[mt], sb + AT_QL + (uint32_t)(row * 272 + seg * 16));
            }
#pragma unroll
            for (int nb = 0; nb < 4; nb++) {
                int rowk = nb * 16 + (lane & 7) + ((lane >> 4) << 3);
                int segk = ks * 2 + ((lane >> 3) & 1);
                uint32_t kh_[4], kl_[4];
                ldmx4(kh_, kb + AT_KH + (uint32_t)(rowk * 272 + segk * 16));
                ldmx4(kl_, kb + AT_KL + (uint32_t)(rowk * 272 + segk * 16));
#pragma unroll
                for (int mt = 0; mt < 2; mt++) {
                    mma16816(sacc[mt][2*nb],   qa_h[mt], kh_[0], kh_[1]);
                    mma16816(sacc[mt][2*nb+1], qa_h[mt], kh_[2], kh_[3]);
                    mma16816(sacc[mt][2*nb],   qa_l[mt], kh_[0], kh_[1]);
                    mma16816(sacc[mt][2*nb+1], qa_l[mt], kh_[2], kh_[3]);
                    mma16816(sacc[mt][2*nb],   qa_h[mt], kl_[0], kl_[1]);
                    mma16816(sacc[mt][2*nb+1], qa_h[mt], kl_[2], kl_[3]);
                }
            }
        }

        // ---- causal mask (only last two tiles can cross the diagonal) ----
        if (kt >= nt - 2) {
#pragma unroll
            for (int mt = 0; mt < 2; mt++)
#pragma unroll
                for (int j = 0; j < 8; j++)
#pragma unroll
                    for (int e = 0; e < 4; e++) {
                        int col = kv0 + j * 8 + 2 * (lane & 3) + (e & 1);
                        int row = q0 + wid * 32 + mt * 16 + (lane >> 2) + 8 * (e >> 1);
                        if (col > row) sacc[mt][j][e] = -1e30f;
                    }
        }

        // ---- online softmax (base-2; log2e folded into Q scale) ----
        float alph[2][2];
#pragma unroll
        for (int mt = 0; mt < 2; mt++) {
#pragma unroll
            for (int half = 0; half < 2; half++) {
                float mx = -1e30f;
#pragma unroll
                for (int j = 0; j < 8; j++)
                    mx = fmaxf(mx, fmaxf(sacc[mt][j][2*half], sacc[mt][j][2*half+1]));
                mx = fmaxf(mx, __shfl_xor_sync(0xffffffffu, mx, 1));
                mx = fmaxf(mx, __shfl_xor_sync(0xffffffffu, mx, 2));
                float mo = mrow[mt][half];
                float mn = fmaxf(mo, mx);
                float al = fexp2(mo - mn);
                float sum = 0.f;
#pragma unroll
                for (int j = 0; j < 8; j++) {
                    float p0 = fexp2(sacc[mt][j][2*half]   - mn);
                    float p1 = fexp2(sacc[mt][j][2*half+1] - mn);
                    sacc[mt][j][2*half] = p0; sacc[mt][j][2*half+1] = p1;
                    sum += p0 + p1;
                }
                sum += __shfl_xor_sync(0xffffffffu, sum, 1);
                sum += __shfl_xor_sync(0xffffffffu, sum, 2);
                mrow[mt][half] = mn;
                lrow[mt][half] = lrow[mt][half] * al + sum;
                alph[mt][half] = al;
            }
#pragma unroll
            for (int n = 0; n < 16; n++) {
                oacc[mt][n][0] *= alph[mt][0]; oacc[mt][n][1] *= alph[mt][0];
                oacc[mt][n][2] *= alph[mt][1]; oacc[mt][n][3] *= alph[mt][1];
            }
        }

        // ---- PV: O += Ph*Vh + Pl*Vh + Ph*Vl (P split hi/lo in bf16) ----
#pragma unroll
        for (int kk = 0; kk < 4; kk++) {
            uint32_t pah[2][4], pal[2][4];
#pragma unroll
            for (int mt = 0; mt < 2; mt++) {
#pragma unroll
                for (int r = 0; r < 4; r++) {
                    int jj = 2*kk + (r >> 1);
                    float a0 = sacc[mt][jj][(r & 1) * 2 + 0];
                    float a1 = sacc[mt][jj][(r & 1) * 2 + 1];
                    uint32_t hp = pack_bf16x2(a0, a1);
                    union { uint32_t u; __nv_bfloat162 b; } cv; cv.u = hp;
                    float h0f = __bfloat162float(cv.b.x);
                    float h1f = __bfloat162float(cv.b.y);
                    pah[mt][r] = hp;
                    pal[mt][r] = pack_bf16x2(a0 - h0f, a1 - h1f);
                }
            }
            int rowv = kk * 16 + ((lane >> 3) & 1) * 8 + (lane & 7);
            int colb = (lane >> 4) * 8;   // within 16-col group
#pragma unroll
            for (int nn = 0; nn < 8; nn++) {
                uint32_t vaddr = (uint32_t)(rowv * 272 + (nn * 16 + colb) * 2);
                uint32_t vh_[4], vl_[4];
                ldmx4t(vh_, kb + AT_VH + vaddr);
                ldmx4t(vl_, kb + AT_VL + vaddr);
#pragma unroll
                for (int mt = 0; mt < 2; mt++) {
                    mma16816(oacc[mt][2*nn],   pah[mt], vh_[0], vh_[1]);
                    mma16816(oacc[mt][2*nn+1], pah[mt], vh_[2], vh_[3]);
                    mma16816(oacc[mt][2*nn],   pal[mt], vh_[0], vh_[1]);
                    mma16816(oacc[mt][2*nn+1], pal[mt], vh_[2], vh_[3]);
                    mma16816(oacc[mt][2*nn],   pah[mt], vl_[0], vl_[1]);
                    mma16816(oacc[mt][2*nn+1], pah[mt], vl_[2], vl_[3]);
                }
            }
        }

        __syncthreads();
        if (kt + 2 < nt) attn_issue_kv(sb, kt & 1, bh, (kt + 2) * 64, tid, Kh, Kl, Vh, Vl);
    }

    // ---- epilogue: ctx = O / l, write bf16 hi/lo at [b*S+s][h*D+d] ----
    const int b = bh >> 4, h = bh & 15;
#pragma unroll
    for (int mt = 0; mt < 2; mt++) {
#pragma unroll
        for (int half = 0; half < 2; half++) {
            float inv = 1.0f / lrow[mt][half];
            int s = q0 + wid * 32 + mt * 16 + (lane >> 2) + 8 * half;
            size_t base = ((size_t)b * S_ + s) * (size_t)E_ + h * D_;
#pragma unroll
            for (int nn = 0; nn < 16; nn++) {
                int c = nn * 8 + 2 * (lane & 3);
                float v0 = oacc[mt][nn][2*half]   * inv;
                float v1 = oacc[mt][nn][2*half+1] * inv;
                __nv_bfloat16 h0 = __float2bfloat16(v0);
                __nv_bfloat16 h1 = __float2bfloat16(v1);
                __nv_bfloat16 l0 = __float2bfloat16(v0 - __bfloat162float(h0));
                __nv_bfloat16 l1 = __float2bfloat16(v1 - __bfloat162float(h1));
                *(__nv_bfloat162*)(Chi + base + c) = __halves2bfloat162(h0, h1);
                *(__nv_bfloat162*)(Clo + base + c) = __halves2bfloat162(l0, l1);
            }
        }
    }
}

// ---------------------------------------------------------------------------
extern "C" void kernel_launch(void* const* d_in, const int* in_sizes, int n_in,
                              void* d_out, int out_size)
{
    const float* q  = (const float*)d_in[0];
    const float* k  = (const float*)d_in[1];
    const float* v  = (const float*)d_in[2];
    const float* Wq = (const float*)d_in[4];
    const float* Wk = (const float*)d_in[5];
    const float* Wv = (const float*)d_in[6];
    const float* Wo = (const float*)d_in[7];
    float* out = (float*)d_out;

    __nv_bfloat16 *qh,*ql,*kh,*kl,*vh,*vl;
    __nv_bfloat16 *wqh,*wql,*wkh,*wkl,*wvh,*wvl,*woh,*wol;
    __nv_bfloat16 *Qph,*Qpl,*Kph,*Kpl,*Vph,*Vpl,*ch,*cl;
    cudaGetSymbolAddress((void**)&qh, g_qh);  cudaGetSymbolAddress((void**)&ql, g_ql);
    cudaGetSymbolAddress((void**)&kh, g_kh);  cudaGetSymbolAddress((void**)&kl, g_kl);
    cudaGetSymbolAddress((void**)&vh, g_vh);  cudaGetSymbolAddress((void**)&vl, g_vl);
    cudaGetSymbolAddress((void**)&wqh, g_wqh); cudaGetSymbolAddress((void**)&wql, g_wql);
    cudaGetSymbolAddress((void**)&wkh, g_wkh); cudaGetSymbolAddress((void**)&wkl, g_wkl);
    cudaGetSymbolAddress((void**)&wvh, g_wvh); cudaGetSymbolAddress((void**)&wvl, g_wvl);
    cudaGetSymbolAddress((void**)&woh, g_woh); cudaGetSymbolAddress((void**)&wol, g_wol);
    cudaGetSymbolAddress((void**)&Qph, g_Qh);  cudaGetSymbolAddress((void**)&Qpl, g_Ql);
    cudaGetSymbolAddress((void**)&Kph, g_Kh);  cudaGetSymbolAddress((void**)&Kpl, g_Kl);
    cudaGetSymbolAddress((void**)&Vph, g_Vh);  cudaGetSymbolAddress((void**)&Vpl, g_Vl);
    cudaGetSymbolAddress((void**)&ch, g_ch);   cudaGetSymbolAddress((void**)&cl, g_cl);

    cudaFuncSetAttribute(gemm_hmma, cudaFuncAttributeMaxDynamicSharedMemorySize, GEMM_SMEM);
    cudaFuncSetAttribute(attn_hmma, cudaFuncAttributeMaxDynamicSharedMemorySize, ATTN_SMEM);

    const int nx4 = M_ * K_ / 4;
    const int nw4 = N_ * K_ / 4;

    split_kernel<<<nx4/256, 256>>>(q, qh, ql, nx4);
    split_kernel<<<nx4/256, 256>>>(k, kh, kl, nx4);
    split_kernel<<<nx4/256, 256>>>(v, vh, vl, nx4);
    split_kernel<<<nw4/256, 256>>>(Wq, wqh, wql, nw4);
    split_kernel<<<nw4/256, 256>>>(Wk, wkh, wkl, nw4);
    split_kernel<<<nw4/256, 256>>>(Wv, wvh, wvl, nw4);
    split_kernel<<<nw4/256, 256>>>(Wo, woh, wol, nw4);

    // scale = log2(e)/sqrt(D): softmax computed base-2 is then exactly softmax(s)
    const float qscale = 0.12751744154070513f;
    dim3 gg(N_/128, M_/128);   // (16, 32)

    gemm_hmma<<<gg, 128, GEMM_SMEM>>>(qh, ql, wqh, wql, nullptr, Qph, Qpl, 1, qscale);
    gemm_hmma<<<gg, 128, GEMM_SMEM>>>(kh, kl, wkh, wkl, nullptr, Kph, Kpl, 1, 1.0f);
    gemm_hmma<<<gg, 128, GEMM_SMEM>>>(vh, vl, wvh, wvl, nullptr, Vph, Vpl, 1, 1.0f);

    attn_hmma<<<dim3(S_/128, B_*H_), 128, ATTN_SMEM>>>(Qph, Qpl, Kph, Kpl, Vph, Vpl, ch, cl);

    gemm_hmma<<<gg, 128, GEMM_SMEM>>>(ch, cl, woh, wol, out, nullptr, nullptr, 0, 1.0f);
}

// round 9
// speedup vs baseline: 2.9891x; 1.0709x over previous
#include <cuda_runtime.h>
#include <cuda_bf16.h>
#include <math.h>
#include <cstdint>

static constexpr int B_ = 2, S_ = 2048, E_ = 2048, H_ = 16, D_ = 128;
static constexpr int M_ = B_ * S_;   // 4096
static constexpr int N_ = E_;        // 2048
static constexpr int K_ = E_;        // 2048

// ---------------- scratch (__device__ globals: allocation-free rule) --------
__device__ __nv_bfloat16 g_qh[M_*K_], g_ql[M_*K_];
__device__ __nv_bfloat16 g_kh[M_*K_], g_kl[M_*K_];
__device__ __nv_bfloat16 g_vh[M_*K_], g_vl[M_*K_];
__device__ __nv_bfloat16 g_wqh[N_*K_], g_wql[N_*K_];
__device__ __nv_bfloat16 g_wkh[N_*K_], g_wkl[N_*K_];
__device__ __nv_bfloat16 g_wvh[N_*K_], g_wvl[N_*K_];
__device__ __nv_bfloat16 g_woh[N_*K_], g_wol[N_*K_];
// projections, head-split [B][H][S][D], hi/lo
__device__ __nv_bfloat16 g_Qh[B_*H_*S_*D_], g_Ql[B_*H_*S_*D_];
__device__ __nv_bfloat16 g_Kh[B_*H_*S_*D_], g_Kl[B_*H_*S_*D_];
__device__ __nv_bfloat16 g_Vh[B_*H_*S_*D_], g_Vl[B_*H_*S_*D_];
// attention output, [m][e] hi/lo
__device__ __nv_bfloat16 g_ch[M_*E_], g_cl[M_*E_];

// ---------------- helpers ---------------------------------------------------
__device__ __forceinline__ uint32_t smem_u32(const void* p) {
    uint32_t a;
    asm("{ .reg .u64 t; cvta.to.shared.u64 t, %1; cvt.u32.u64 %0, t; }" : "=r"(a) : "l"(p));
    return a;
}
__device__ __forceinline__ void ldmx4(uint32_t* r, uint32_t addr) {
    asm volatile("ldmatrix.sync.aligned.m8n8.x4.shared.b16 {%0,%1,%2,%3}, [%4];"
        : "=r"(r[0]), "=r"(r[1]), "=r"(r[2]), "=r"(r[3]) : "r"(addr));
}
__device__ __forceinline__ void ldmx4t(uint32_t* r, uint32_t addr) {
    asm volatile("ldmatrix.sync.aligned.m8n8.x4.trans.shared.b16 {%0,%1,%2,%3}, [%4];"
        : "=r"(r[0]), "=r"(r[1]), "=r"(r[2]), "=r"(r[3]) : "r"(addr));
}
__device__ __forceinline__ void mma16816(float* c, const uint32_t* a, uint32_t b0, uint32_t b1) {
    asm volatile("mma.sync.aligned.m16n8k16.row.col.f32.bf16.bf16.f32 "
        "{%0,%1,%2,%3}, {%4,%5,%6,%7}, {%8,%9}, {%0,%1,%2,%3};"
        : "+f"(c[0]), "+f"(c[1]), "+f"(c[2]), "+f"(c[3])
        : "r"(a[0]), "r"(a[1]), "r"(a[2]), "r"(a[3]), "r"(b0), "r"(b1));
}
__device__ __forceinline__ uint32_t pack_bf16x2(float lo, float hi) {
    uint32_t d;
    asm("cvt.rn.bf16x2.f32 %0, %1, %2;" : "=r"(d) : "f"(hi), "f"(lo));
    return d;
}
// fast exp2 on the FMA pipe (no MUFU). t <= 0 expected; clamped at -80.
__device__ __forceinline__ float fexp2(float t) {
    t = fmaxf(t, -80.0f);
    float r  = __fadd_rn(t, 12582912.0f);         // 1.5*2^23 magic round
    int   i  = __float_as_int(r) - 0x4B400000;
    float rf = __fadd_rn(r, -12582912.0f);
    float f  = __fadd_rn(t, -rf);                 // f in [-0.5, 0.5]
    float p  = 0.0013333558f;
    p = fmaf(p, f, 0.0096181291f);
    p = fmaf(p, f, 0.0555041087f);
    p = fmaf(p, f, 0.2402265069f);
    p = fmaf(p, f, 0.6931471806f);
    p = fmaf(p, f, 1.0f);
    return __int_as_float(__float_as_int(p) + (i << 23));
}

// ---------------- fp32 -> (hi, lo) bf16 splits (fused multi-tensor) ---------
__device__ __forceinline__ void split_one(const float* __restrict__ x,
    __nv_bfloat16* __restrict__ hi, __nv_bfloat16* __restrict__ lo, int i)
{
    float4 v = ((const float4*)x)[i];
    __nv_bfloat16 h0 = __float2bfloat16(v.x);
    __nv_bfloat16 h1 = __float2bfloat16(v.y);
    __nv_bfloat16 h2 = __float2bfloat16(v.z);
    __nv_bfloat16 h3 = __float2bfloat16(v.w);
    __nv_bfloat16 l0 = __float2bfloat16(v.x - __bfloat162float(h0));
    __nv_bfloat16 l1 = __float2bfloat16(v.y - __bfloat162float(h1));
    __nv_bfloat16 l2 = __float2bfloat16(v.z - __bfloat162float(h2));
    __nv_bfloat16 l3 = __float2bfloat16(v.w - __bfloat162float(h3));
    ((__nv_bfloat162*)hi)[i*2]   = __halves2bfloat162(h0, h1);
    ((__nv_bfloat162*)hi)[i*2+1] = __halves2bfloat162(h2, h3);
    ((__nv_bfloat162*)lo)[i*2]   = __halves2bfloat162(l0, l1);
    ((__nv_bfloat162*)lo)[i*2+1] = __halves2bfloat162(l2, l3);
}

__global__ __launch_bounds__(256)
void split3_kernel(const float* __restrict__ x0, __nv_bfloat16* h0, __nv_bfloat16* l0,
                   const float* __restrict__ x1, __nv_bfloat16* h1, __nv_bfloat16* l1,
                   const float* __restrict__ x2, __nv_bfloat16* h2, __nv_bfloat16* l2,
                   int n4)
{
    int i = blockIdx.x * 256 + threadIdx.x;
    if (i >= n4) return;
    int t = blockIdx.y;
    if (t == 0)      split_one(x0, h0, l0, i);
    else if (t == 1) split_one(x1, h1, l1, i);
    else             split_one(x2, h2, l2, i);
}

__global__ __launch_bounds__(256)
void split4_kernel(const float* __restrict__ x0, __nv_bfloat16* h0, __nv_bfloat16* l0,
                   const float* __restrict__ x1, __nv_bfloat16* h1, __nv_bfloat16* l1,
                   const float* __restrict__ x2, __nv_bfloat16* h2, __nv_bfloat16* l2,
                   const float* __restrict__ x3, __nv_bfloat16* h3, __nv_bfloat16* l3,
                   int n4)
{
    int i = blockIdx.x * 256 + threadIdx.x;
    if (i >= n4) return;
    int t = blockIdx.y;
    if (t == 0)      split_one(x0, h0, l0, i);
    else if (t == 1) split_one(x1, h1, l1, i);
    else if (t == 2) split_one(x2, h2, l2, i);
    else             split_one(x3, h3, l3, i);
}

// ---------------- HMMA GEMM: C = A @ W^T (3-pass bf16 split) ----------------
// 128x128 tile, BK=32, 128 threads (4 warps of 64x64), 4-stage cp.async.
static constexpr int GEMM_SMEM = 4 * 16384;   // 65536

__global__ __launch_bounds__(128, 2)
void gemm_hmma(const __nv_bfloat16* __restrict__ Ah, const __nv_bfloat16* __restrict__ Al,
               const __nv_bfloat16* __restrict__ Wh, const __nv_bfloat16* __restrict__ Wl,
               float* __restrict__ Cf, __nv_bfloat16* __restrict__ Chi,
               __nv_bfloat16* __restrict__ Clo, int mode, float scale)
{
    extern __shared__ char sm[];
    const uint32_t sbase = smem_u32(sm);
    const int tid  = threadIdx.x;
    const int lane = tid & 31, wid = tid >> 5;
    const int wm = wid & 1, wn = wid >> 1;       // warp tile: rows 64*wm, cols 64*wn
    const int m0 = blockIdx.y * 128;
    const int n0 = blockIdx.x * 128;

    float acc[4][8][4];
#pragma unroll
    for (int i = 0; i < 4; i++)
#pragma unroll
        for (int j = 0; j < 8; j++)
#pragma unroll
            for (int t = 0; t < 4; t++) acc[i][j][t] = 0.f;

    const int crow = tid >> 2, cseg = tid & 3;

    const int NITER = 192;   // 3 passes x 64 k-iters of BK=32

#define G_ISSUE(it) do { \
        int pass_ = (it) >> 6; int kb_ = ((it) & 63) << 5; \
        const __nv_bfloat16* Ap_ = (pass_ == 2) ? Al : Ah; \
        const __nv_bfloat16* Wp_ = (pass_ == 1) ? Wl : Wh; \
        uint32_t st_ = sbase + (uint32_t)(((it) & 3) * 16384); \
        _Pragma("unroll") \
        for (int j_ = 0; j_ < 4; j_++) { \
            int row_ = crow + j_ * 32; \
            uint32_t off_ = (uint32_t)row_ * 64u + (uint32_t)((cseg ^ ((row_ >> 1) & 3)) << 4); \
            const void* ga_ = Ap_ + (size_t)(m0 + row_) * K_ + kb_ + cseg * 8; \
            const void* gb_ = Wp_ + (size_t)(n0 + row_) * K_ + kb_ + cseg * 8; \
            asm volatile("cp.async.cg.shared.global [%0], [%1], 16;" :: "r"(st_ + off_), "l"(ga_)); \
            asm volatile("cp.async.cg.shared.global [%0], [%1], 16;" :: "r"(st_ + 8192u + off_), "l"(gb_)); \
        } \
        asm volatile("cp.async.commit_group;"); \
    } while (0)

    G_ISSUE(0); G_ISSUE(1); G_ISSUE(2);

    const int rowA0 = wm * 64 + (lane & 7) + (lane & 8);
    const int asegb = (lane >> 4);
    const int rowB0 = wn * 64 + (lane & 7) + ((lane >> 4) << 3);
    const int bsegb = (lane >> 3) & 1;

    for (int it = 0; it < NITER; it++) {
        if (it < NITER - 2)      { asm volatile("cp.async.wait_group 2;" ::: "memory"); }
        else if (it == NITER - 2){ asm volatile("cp.async.wait_group 1;" ::: "memory"); }
        else                     { asm volatile("cp.async.wait_group 0;" ::: "memory"); }
        __syncthreads();
        if (it + 3 < NITER) G_ISSUE(it + 3);

        const uint32_t ab = sbase + (uint32_t)((it & 3) * 16384);
        const uint32_t bb = ab + 8192u;

#pragma unroll
        for (int ks = 0; ks < 2; ks++) {
            uint32_t a[4][4];
#pragma unroll
            for (int mt = 0; mt < 4; mt++) {
                int row = rowA0 + mt * 16;
                int sl = ks * 2 + asegb;
                ldmx4(a[mt], ab + (uint32_t)row * 64u + (uint32_t)((sl ^ ((row >> 1) & 3)) << 4));
            }
#pragma unroll
            for (int nb = 0; nb < 4; nb++) {
                int row = rowB0 + nb * 16;
                int sl = ks * 2 + bsegb;
                uint32_t b[4];
                ldmx4(b, bb + (uint32_t)row * 64u + (uint32_t)((sl ^ ((row >> 1) & 3)) << 4));
#pragma unroll
                for (int mt = 0; mt < 4; mt++) {
                    mma16816(acc[mt][2*nb],   a[mt], b[0], b[1]);
                    mma16816(acc[mt][2*nb+1], a[mt], b[2], b[3]);
                }
            }
        }
    }
#undef G_ISSUE

    // ---- epilogue ----
#pragma unroll
    for (int mt = 0; mt < 4; mt++) {
#pragma unroll
        for (int half = 0; half < 2; half++) {
            int m = m0 + wm * 64 + mt * 16 + (lane >> 2) + half * 8;
            if (mode == 1) {
                int b = m >> 11, s = m & (S_ - 1);
                int h = blockIdx.x;
                size_t base = (((size_t)(b * H_ + h)) * S_ + s) * (size_t)D_;
#pragma unroll
                for (int n8 = 0; n8 < 8; n8++) {
                    int c = wn * 64 + n8 * 8 + 2 * (lane & 3);
                    float v0 = acc[mt][n8][half*2]   * scale;
                    float v1 = acc[mt][n8][half*2+1] * scale;
                    __nv_bfloat16 h0 = __float2bfloat16(v0);
                    __nv_bfloat16 h1 = __float2bfloat16(v1);
                    __nv_bfloat16 l0 = __float2bfloat16(v0 - __bfloat162float(h0));
                    __nv_bfloat16 l1 = __float2bfloat16(v1 - __bfloat162float(h1));
                    *(__nv_bfloat162*)(Chi + base + c) = __halves2bfloat162(h0, h1);
                    *(__nv_bfloat162*)(Clo + base + c) = __halves2bfloat162(l0, l1);
                }
            } else {
#pragma unroll
                for (int n8 = 0; n8 < 8; n8++) {
                    int c = wn * 64 + n8 * 8 + 2 * (lane & 3);
                    float2 v;
                    v.x = acc[mt][n8][half*2];
                    v.y = acc[mt][n8][half*2+1];
                    *(float2*)(Cf + (size_t)m * N_ + n0 + c) = v;
                }
            }
        }
    }
}

// ---------------- HMMA flash attention --------------------------------------
// CTA: 256 threads (8 warps, 16 q-rows each), Br=128, Bc=64, D=128.
// Scores 3-pass hi/lo; P hi/lo; PV 3-pass.
static constexpr int AT_QH  = 0;
static constexpr int AT_QL  = 34816;
static constexpr int AT_KV0 = 69632;       // stage stride 69632
static constexpr int AT_KH = 0, AT_KL = 17408, AT_VH = 34816, AT_VL = 52224;
static constexpr int ATTN_SMEM = AT_KV0 + 2 * 69632;   // 208896

__device__ __forceinline__ void attn_issue_kv(
    uint32_t sb, int stage, int bh, int kv0, int tid,
    const __nv_bfloat16* Kh, const __nv_bfloat16* Kl,
    const __nv_bfloat16* Vh, const __nv_bfloat16* Vl)
{
    uint32_t kb = sb + AT_KV0 + (uint32_t)(stage * 69632);
    const __nv_bfloat16* srcs[4] = {Kh, Kl, Vh, Vl};
    const uint32_t offs[4] = {AT_KH, AT_KL, AT_VH, AT_VL};
#pragma unroll
    for (int m = 0; m < 4; m++) {
        const __nv_bfloat16* src = srcs[m] + ((size_t)bh * S_ + kv0) * D_;
#pragma unroll
        for (int j = 0; j < 4; j++) {
            int idx = tid + j * 256;
            int row = idx >> 4, seg = idx & 15;
            const void* g = src + (size_t)row * D_ + seg * 8;
            asm volatile("cp.async.cg.shared.global [%0], [%1], 16;"
                :: "r"(kb + offs[m] + (uint32_t)(row * 272 + seg * 16)), "l"(g));
        }
    }
    asm volatile("cp.async.commit_group;");
}

__global__ __launch_bounds__(256)
void attn_hmma(const __nv_bfloat16* __restrict__ Qh, const __nv_bfloat16* __restrict__ Ql,
               const __nv_bfloat16* __restrict__ Kh, const __nv_bfloat16* __restrict__ Kl,
               const __nv_bfloat16* __restrict__ Vh, const __nv_bfloat16* __restrict__ Vl,
               __nv_bfloat16* __restrict__ Chi, __nv_bfloat16* __restrict__ Clo)
{
    extern __shared__ char sm[];
    const uint32_t sb = smem_u32(sm);
    const int tid = threadIdx.x;
    const int lane = tid & 31, wid = tid >> 5;   // wid 0..7, rows 16*wid
    const int qt = (int)gridDim.x - 1 - (int)blockIdx.x;   // heavy tiles first
    const int bh = blockIdx.y;
    const int q0 = qt * 128;
    const int nt = 2 * qt + 2;

    // ---- load Q (hi+lo) as its own cp.async group ----
    {
        const __nv_bfloat16* qsrc[2] = {Qh + ((size_t)bh * S_ + q0) * D_,
                                        Ql + ((size_t)bh * S_ + q0) * D_};
        const uint32_t qoff[2] = {AT_QH, AT_QL};
#pragma unroll
        for (int m = 0; m < 2; m++) {
#pragma unroll
            for (int j = 0; j < 8; j++) {
                int idx = tid + j * 256;
                int row = idx >> 4, seg = idx & 15;
                const void* g = qsrc[m] + (size_t)row * D_ + seg * 8;
                asm volatile("cp.async.cg.shared.global [%0], [%1], 16;"
                    :: "r"(sb + qoff[m] + (uint32_t)(row * 272 + seg * 16)), "l"(g));
            }
        }
        asm volatile("cp.async.commit_group;");
    }
    attn_issue_kv(sb, 0, bh, 0, tid, Kh, Kl, Vh, Vl);
    if (nt > 1) attn_issue_kv(sb, 1, bh, 64, tid, Kh, Kl, Vh, Vl);

    float oacc[16][4];
#pragma unroll
    for (int n = 0; n < 16; n++)
#pragma unroll
        for (int t = 0; t < 4; t++) oacc[n][t] = 0.f;
    float mrow[2] = {-1e30f, -1e30f};
    float lrow[2] = {0.f, 0.f};

    for (int kt = 0; kt < nt; kt++) {
        const int kv0 = kt * 64;
        if (kt + 1 < nt) { asm volatile("cp.async.wait_group 1;" ::: "memory"); }
        else             { asm volatile("cp.async.wait_group 0;" ::: "memory"); }
        __syncthreads();
        const uint32_t kb = sb + AT_KV0 + (uint32_t)((kt & 1) * 69632);

        // ---- scores: S = Qh*Kh^T + Qh*Kl^T + Ql*Kh^T ----
        float sacc[8][4];
#pragma unroll
        for (int j = 0; j < 8; j++)
#pragma unroll
            for (int t = 0; t < 4; t++) sacc[j][t] = 0.f;

#pragma unroll
        for (int ks = 0; ks < 8; ks++) {
            uint32_t qa_h[4], qa_l[4];
            {
                int row = wid * 16 + (lane & 7) + (lane & 8);
                int seg = ks * 2 + (lane >> 4);
                ldmx4(qa_h, sb + AT_QH + (uint32_t)(row * 272 + seg * 16));
                ldmx4(qa_l, sb + AT_QL + (uint32_t)(row * 272 + seg * 16));
            }
#pragma unroll
            for (int nb = 0; nb < 4; nb++) {
                int rowk = nb * 16 + (lane & 7) + ((lane >> 4) << 3);
                int segk = ks * 2 + ((lane >> 3) & 1);
                uint32_t kh_[4], kl_[4];
                ldmx4(kh_, kb + AT_KH + (uint32_t)(rowk * 272 + segk * 16));
                ldmx4(kl_, kb + AT_KL + (uint32_t)(rowk * 272 + segk * 16));
                mma16816(sacc[2*nb],   qa_h, kh_[0], kh_[1]);
                mma16816(sacc[2*nb+1], qa_h, kh_[2], kh_[3]);
                mma16816(sacc[2*nb],   qa_l, kh_[0], kh_[1]);
                mma16816(sacc[2*nb+1], qa_l, kh_[2], kh_[3]);
                mma16816(sacc[2*nb],   qa_h, kl_[0], kl_[1]);
                mma16816(sacc[2*nb+1], qa_h, kl_[2], kl_[3]);
            }
        }

        // ---- causal mask (only last two tiles can cross the diagonal) ----
        if (kt >= nt - 2) {
#pragma unroll
            for (int j = 0; j < 8; j++)
#pragma unroll
                for (int e = 0; e < 4; e++) {
                    int col = kv0 + j * 8 + 2 * (lane & 3) + (e & 1);
                    int row = q0 + wid * 16 + (lane >> 2) + 8 * (e >> 1);
                    if (col > row) sacc[j][e] = -1e30f;
                }
        }

        // ---- online softmax (base-2; log2e folded into Q scale) ----
        float alph[2];
#pragma unroll
        for (int half = 0; half < 2; half++) {
            float mx = -1e30f;
#pragma unroll
            for (int j = 0; j < 8; j++)
                mx = fmaxf(mx, fmaxf(sacc[j][2*half], sacc[j][2*half+1]));
            mx = fmaxf(mx, __shfl_xor_sync(0xffffffffu, mx, 1));
            mx = fmaxf(mx, __shfl_xor_sync(0xffffffffu, mx, 2));
            float mo = mrow[half];
            float mn = fmaxf(mo, mx);
            float al = fexp2(mo - mn);
            float sum = 0.f;
#pragma unroll
            for (int j = 0; j < 8; j++) {
                float p0 = fexp2(sacc[j][2*half]   - mn);
                float p1 = fexp2(sacc[j][2*half+1] - mn);
                sacc[j][2*half] = p0; sacc[j][2*half+1] = p1;
                sum += p0 + p1;
            }
            sum += __shfl_xor_sync(0xffffffffu, sum, 1);
            sum += __shfl_xor_sync(0xffffffffu, sum, 2);
            mrow[half] = mn;
            lrow[half] = lrow[half] * al + sum;
            alph[half] = al;
        }
#pragma unroll
        for (int n = 0; n < 16; n++) {
            oacc[n][0] *= alph[0]; oacc[n][1] *= alph[0];
            oacc[n][2] *= alph[1]; oacc[n][3] *= alph[1];
        }

        // ---- PV: O += Ph*Vh + Pl*Vh + Ph*Vl (P split hi/lo in bf16) ----
#pragma unroll
        for (int kk = 0; kk < 4; kk++) {
            uint32_t pah[4], pal[4];
#pragma unroll
            for (int r = 0; r < 4; r++) {
                int jj = 2*kk + (r >> 1);
                float a0 = sacc[jj][(r & 1) * 2 + 0];
                float a1 = sacc[jj][(r & 1) * 2 + 1];
                uint32_t hp = pack_bf16x2(a0, a1);
                union { uint32_t u; __nv_bfloat162 b; } cv; cv.u = hp;
                float h0f = __bfloat162float(cv.b.x);
                float h1f = __bfloat162float(cv.b.y);
                pah[r] = hp;
                pal[r] = pack_bf16x2(a0 - h0f, a1 - h1f);
            }
            int rowv = kk * 16 + ((lane >> 3) & 1) * 8 + (lane & 7);
            int colb = (lane >> 4) * 8;   // within 16-col group
#pragma unroll
            for (int nn = 0; nn < 8; nn++) {
                uint32_t vaddr = (uint32_t)(rowv * 272 + (nn * 16 + colb) * 2);
                uint32_t vh_[4], vl_[4];
                ldmx4t(vh_, kb + AT_VH + vaddr);
                ldmx4t(vl_, kb + AT_VL + vaddr);
                mma16816(oacc[2*nn],   pah, vh_[0], vh_[1]);
                mma16816(oacc[2*nn+1], pah, vh_[2], vh_[3]);
                mma16816(oacc[2*nn],   pal, vh_[0], vh_[1]);
                mma16816(oacc[2*nn+1], pal, vh_[2], vh_[3]);
                mma16816(oacc[2*nn],   pah, vl_[0], vl_[1]);
                mma16816(oacc[2*nn+1], pah, vl_[2], vl_[3]);
            }
        }

        __syncthreads();
        if (kt + 2 < nt) attn_issue_kv(sb, kt & 1, bh, (kt + 2) * 64, tid, Kh, Kl, Vh, Vl);
    }

    // ---- epilogue: ctx = O / l, write bf16 hi/lo at [b*S+s][h*D+d] ----
    const int b = bh >> 4, h = bh & 15;
#pragma unroll
    for (int half = 0; half < 2; half++) {
        float inv = 1.0f / lrow[half];
        int s = q0 + wid * 16 + (lane >> 2) + 8 * half;
        size_t base = ((size_t)b * S_ + s) * (size_t)E_ + h * D_;
#pragma unroll
        for (int nn = 0; nn < 16; nn++) {
            int c = nn * 8 + 2 * (lane & 3);
            float v0 = oacc[nn][2*half]   * inv;
            float v1 = oacc[nn][2*half+1] * inv;
            __nv_bfloat16 h0 = __float2bfloat16(v0);
            __nv_bfloat16 h1 = __float2bfloat16(v1);
            __nv_bfloat16 l0 = __float2bfloat16(v0 - __bfloat162float(h0));
            __nv_bfloat16 l1 = __float2bfloat16(v1 - __bfloat162float(h1));
            *(__nv_bfloat162*)(Chi + base + c) = __halves2bfloat162(h0, h1);
            *(__nv_bfloat162*)(Clo + base + c) = __halves2bfloat162(l0, l1);
        }
    }
}

// ---------------------------------------------------------------------------
extern "C" void kernel_launch(void* const* d_in, const int* in_sizes, int n_in,
                              void* d_out, int out_size)
{
    const float* q  = (const float*)d_in[0];
    const float* k  = (const float*)d_in[1];
    const float* v  = (const float*)d_in[2];
    const float* Wq = (const float*)d_in[4];
    const float* Wk = (const float*)d_in[5];
    const float* Wv = (const float*)d_in[6];
    const float* Wo = (const float*)d_in[7];
    float* out = (float*)d_out;

    __nv_bfloat16 *qh,*ql,*kh,*kl,*vh,*vl;
    __nv_bfloat16 *wqh,*wql,*wkh,*wkl,*wvh,*wvl,*woh,*wol;
    __nv_bfloat16 *Qph,*Qpl,*Kph,*Kpl,*Vph,*Vpl,*ch,*cl;
    cudaGetSymbolAddress((void**)&qh, g_qh);  cudaGetSymbolAddress((void**)&ql, g_ql);
    cudaGetSymbolAddress((void**)&kh, g_kh);  cudaGetSymbolAddress((void**)&kl, g_kl);
    cudaGetSymbolAddress((void**)&vh, g_vh);  cudaGetSymbolAddress((void**)&vl, g_vl);
    cudaGetSymbolAddress((void**)&wqh, g_wqh); cudaGetSymbolAddress((void**)&wql, g_wql);
    cudaGetSymbolAddress((void**)&wkh, g_wkh); cudaGetSymbolAddress((void**)&wkl, g_wkl);
    cudaGetSymbolAddress((void**)&wvh, g_wvh); cudaGetSymbolAddress((void**)&wvl, g_wvl);
    cudaGetSymbolAddress((void**)&woh, g_woh); cudaGetSymbolAddress((void**)&wol, g_wol);
    cudaGetSymbolAddress((void**)&Qph, g_Qh);  cudaGetSymbolAddress((void**)&Qpl, g_Ql);
    cudaGetSymbolAddress((void**)&Kph, g_Kh);  cudaGetSymbolAddress((void**)&Kpl, g_Kl);
    cudaGetSymbolAddress((void**)&Vph, g_Vh);  cudaGetSymbolAddress((void**)&Vpl, g_Vl);
    cudaGetSymbolAddress((void**)&ch, g_ch);   cudaGetSymbolAddress((void**)&cl, g_cl);

    cudaFuncSetAttribute(gemm_hmma, cudaFuncAttributeMaxDynamicSharedMemorySize, GEMM_SMEM);
    cudaFuncSetAttribute(attn_hmma, cudaFuncAttributeMaxDynamicSharedMemorySize, ATTN_SMEM);

    const int nx4 = M_ * K_ / 4;
    const int nw4 = N_ * K_ / 4;

    split3_kernel<<<dim3(nx4/256, 3), 256>>>(q, qh, ql, k, kh, kl, v, vh, vl, nx4);
    split4_kernel<<<dim3(nw4/256, 4), 256>>>(Wq, wqh, wql, Wk, wkh, wkl,
                                             Wv, wvh, wvl, Wo, woh, wol, nw4);

    // scale = log2(e)/sqrt(D): softmax computed base-2 is then exactly softmax(s)
    const float qscale = 0.12751744154070513f;
    dim3 gg(N_/128, M_/128);   // (16, 32)

    gemm_hmma<<<gg, 128, GEMM_SMEM>>>(qh, ql, wqh, wql, nullptr, Qph, Qpl, 1, qscale);
    gemm_hmma<<<gg, 128, GEMM_SMEM>>>(kh, kl, wkh, wkl, nullptr, Kph, Kpl, 1, 1.0f);
    gemm_hmma<<<gg, 128, GEMM_SMEM>>>(vh, vl, wvh, wvl, nullptr, Vph, Vpl, 1, 1.0f);

    attn_hmma<<<dim3(S_/128, B_*H_), 256, ATTN_SMEM>>>(Qph, Qpl, Kph, Kpl, Vph, Vpl, ch, cl);

    gemm_hmma<<<gg, 128, GEMM_SMEM>>>(ch, cl, woh, wol, out, nullptr, nullptr, 0, 1.0f);
}